// round 13
// baseline (speedup 1.0000x reference)
#include <cuda_runtime.h>
#include <math.h>

// Problem constants
#define NB 2
#define NV 5023
#define NF 2048
#define IH 256
#define IW 256
#define PP (IH * IW)
#define TF 256               // faces per smem chunk
#define NCHUNK (NF / TF)     // 8
#define SPLIT 2              // face-partition blocks per tile
#define NTHR 128
#define SORT_THR 1024
#define FPB (NF / SORT_THR)  // 2

// preA block layout (256 threads each)
#define PREA_THR 256
#define FACE_BLKS ((NB * NF + PREA_THR - 1) / PREA_THR)                   // 16
#define FATTR_BLKS ((NB * NF * 3 + PREA_THR - 1) / PREA_THR)              // 48
#define ZINIT_PER 16
#define ZINIT_BLKS ((NB * PP + PREA_THR * ZINIT_PER - 1) / (PREA_THR * ZINIT_PER)) // 32

// Unsorted face records (written by preA)
__device__ float4 g_u0[NB * NF];
__device__ float4 g_u1[NB * NF];
__device__ float4 g_u2[NB * NF];
__device__ float4 g_ub[NB * NF];
// Sorted face records (written by preB)
__device__ float4 g_q0[NB * NF];  // A0,B0,A1,B1
__device__ float4 g_q1[NB * NF];  // x2,y2,inv,zmax
__device__ float4 g_q2[NB * NF];  // z0,z1,z2,face_id(bits)
__device__ float4 g_qb[NB * NF];  // xmin,xmax,ymin,ymax
__device__ float g_chunkbound[NB * NCHUNK];   // per-parity suffix max
// Per-face shading attrs: 6 x float4 per (b,f):
//   [6k+2v]   = (vcol_v.r, vcol_v.g, vcol_v.b, vert_v.x)
//   [6k+2v+1] = (vert_v.y, vert_v.z, tvert_v.x, tvert_v.y)
__device__ float4 g_fattr[6 * NB * NF];
__device__ unsigned long long g_zfid[NB * PP]; // (enc(z)<<32)|~fid

__device__ __forceinline__ unsigned encf(float x) {
    unsigned u = __float_as_uint(x);
    return (u & 0x80000000u) ? ~u : (u | 0x80000000u);
}
__device__ __forceinline__ float decf(unsigned e) {
    unsigned u = (e & 0x80000000u) ? (e & 0x7FFFFFFFu) : ~e;
    return __uint_as_float(u);
}
__device__ __forceinline__ int zbucket(float zmx) {
    int bi = (int)((1.0f - zmx) * 127.5f);
    return min(max(bi, 0), 255);
}

// bilinear texture sample for one vertex (reference expression tree)
__device__ __forceinline__ void sample_vcol(const float* __restrict__ tex,
                                            const float* __restrict__ uv,
                                            int b, int v, float col[3]) {
    float u = uv[v * 2 + 0] * 255.0f;
    float vv = uv[v * 2 + 1] * 255.0f;
    float u0f = floorf(u);
    float v0f = floorf(vv);
    u0f = fminf(fmaxf(u0f, 0.0f), 254.0f);
    v0f = fminf(fmaxf(v0f, 0.0f), 254.0f);
    int u0 = (int)u0f;
    int v0 = (int)v0f;
    float fu = u - u0f;
    float fv = vv - v0f;
    const float* t = tex + (size_t)b * 256 * 256 * 3;
    const float* r0 = t + ((size_t)v0 * 256 + u0) * 3;
    const float* r1 = t + ((size_t)(v0 + 1) * 256 + u0) * 3;
#pragma unroll
    for (int c = 0; c < 3; c++) {
        float c00 = r0[c];
        float c01 = r0[3 + c];
        float c10 = r1[c];
        float c11 = r1[3 + c];
        float top = c00 * (1.0f - fu) + c01 * fu;
        float bot = c10 * (1.0f - fu) + c11 * fu;
        col[c] = top * (1.0f - fv) + bot * fv;
    }
}

// ---- preA: face records + per-(face,vertex) shading attrs + zfid init ----
__global__ void __launch_bounds__(PREA_THR) preA(const float* __restrict__ tv,
                                                 const int* __restrict__ faces,
                                                 const float* __restrict__ tex,
                                                 const float* __restrict__ uv,
                                                 const float* __restrict__ verts) {
    const int tid = threadIdx.x;

    if (blockIdx.x < FACE_BLKS) {
        int idx = blockIdx.x * PREA_THR + tid;
        if (idx >= NB * NF) return;
        int b = idx / NF, f = idx % NF;
        int i0 = faces[f * 3 + 0];
        int i1 = faces[f * 3 + 1];
        int i2 = faces[f * 3 + 2];
        const float* p0 = tv + ((size_t)b * NV + i0) * 3;
        const float* p1 = tv + ((size_t)b * NV + i1) * 3;
        const float* p2 = tv + ((size_t)b * NV + i2) * 3;
        float x0 = p0[0], y0 = p0[1], z0 = p0[2];
        float x1 = p1[0], y1 = p1[1], z1 = p1[2];
        float x2 = p2[0], y2 = p2[1], z2 = p2[2];

        float denom = (y1 - y2) * (x0 - x2) + (x2 - x1) * (y0 - y2);
        bool valid = fabsf(denom) > 1e-8f;
        float inv = valid ? (1.0f / denom) : 0.0f;

        float xmn = fminf(x0, fminf(x1, x2));
        float xmx = fmaxf(x0, fmaxf(x1, x2));
        float ymn = fminf(y0, fminf(y1, y2));
        float ymx = fmaxf(y0, fmaxf(y1, y2));
        float zmx = fmaxf(z0, fmaxf(z1, z2));
        if (!valid) { xmn = 2e30f; xmx = -2e30f; ymn = 2e30f; ymx = -2e30f; zmx = -3e30f; }

        g_u0[idx] = make_float4(y1 - y2, x2 - x1, y2 - y0, x0 - x2);
        g_u1[idx] = make_float4(x2, y2, inv, zmx);
        g_u2[idx] = make_float4(z0, z1, z2, __int_as_float(f));
        g_ub[idx] = make_float4(xmn, xmx, ymn, ymx);
        return;
    }

    if (blockIdx.x < FACE_BLKS + FATTR_BLKS) {
        // one thread per (b, f, k): single sample chain each
        int idx = (blockIdx.x - FACE_BLKS) * PREA_THR + tid;
        if (idx >= NB * NF * 3) return;
        int b = idx / (NF * 3);
        int rem = idx % (NF * 3);
        int f = rem / 3;
        int k = rem % 3;
        int vid = faces[f * 3 + k];
        float col[3];
        sample_vcol(tex, uv, b, vid, col);
        const float* vp = verts + ((size_t)(b * NV + vid)) * 3;
        const float* tp = tv + ((size_t)(b * NV + vid)) * 3;
        int go = 6 * (b * NF + f) + 2 * k;
        g_fattr[go + 0] = make_float4(col[0], col[1], col[2], vp[0]);
        g_fattr[go + 1] = make_float4(vp[1], vp[2], tp[0], tp[1]);
        return;
    }

    // zfid init
    {
        const unsigned long long initv = ((unsigned long long)encf(-1.0f) << 32) | 0ull;
        int base = (blockIdx.x - FACE_BLKS - FATTR_BLKS) * PREA_THR * ZINIT_PER + tid;
#pragma unroll
        for (int k = 0; k < ZINIT_PER; k++) {
            int i = base + k * PREA_THR;
            if (i < NB * PP) g_zfid[i] = initv;
        }
    }
}

// ---- preB: counting sort (1 block per batch); records prefetched before scan ----
__global__ void __launch_bounds__(SORT_THR) preB() {
    __shared__ int hist[256];
    __shared__ int offs[256];
    __shared__ int warpTot[8];
    __shared__ unsigned chunkmaxEnc[NCHUNK];
    const int b = blockIdx.x;
    const int tid = threadIdx.x;

    if (tid < 256) hist[tid] = 0;
    if (tid < NCHUNK) chunkmaxEnc[tid] = 0u;

    float4 rq0[FPB], rq1[FPB], rq2[FPB], rqb[FPB];
    int rbkt[FPB];
#pragma unroll
    for (int k = 0; k < FPB; k++) {
        int gi = b * NF + tid + k * SORT_THR;
        rq0[k] = g_u0[gi];
        rq1[k] = g_u1[gi];
        rq2[k] = g_u2[gi];
        rqb[k] = g_ub[gi];
        rbkt[k] = zbucket(rq1[k].w);
    }
    __syncthreads();

#pragma unroll
    for (int k = 0; k < FPB; k++) atomicAdd(&hist[rbkt[k]], 1);
    __syncthreads();

    // hierarchical exclusive scan over 256 buckets (3 syncs)
    int myVal = 0, wIncl = 0;
    if (tid < 256) {
        myVal = hist[tid];
        wIncl = myVal;
#pragma unroll
        for (int s = 1; s < 32; s <<= 1) {
            int n = __shfl_up_sync(0xffffffffu, wIncl, s);
            if ((tid & 31) >= s) wIncl += n;
        }
        if ((tid & 31) == 31) warpTot[tid >> 5] = wIncl;
    }
    __syncthreads();
    if (tid < 8) {
        int t = warpTot[tid];
        int incl = t;
#pragma unroll
        for (int s = 1; s < 8; s <<= 1) {
            int n = __shfl_up_sync(0xffu, incl, s);
            if (tid >= s) incl += n;
        }
        warpTot[tid] = incl - t;
    }
    __syncthreads();
    if (tid < 256) offs[tid] = warpTot[tid >> 5] + wIncl - myVal;
    __syncthreads();

#pragma unroll
    for (int k = 0; k < FPB; k++) {
        int pos = atomicAdd(&offs[rbkt[k]], 1);
        int go = b * NF + pos;
        g_q0[go] = rq0[k];
        g_q1[go] = rq1[k];
        g_q2[go] = rq2[k];
        g_qb[go] = rqb[k];
        atomicMax(&chunkmaxEnc[pos / TF], encf(rq1[k].w));
    }
    __syncthreads();

    if (tid == 0) {
#pragma unroll
        for (int s = 0; s < SPLIT; s++) {
            float bound = -3e30f;
            for (int c = NCHUNK - SPLIT + s; c >= 0; c -= SPLIT) {
                bound = fmaxf(bound, decf(chunkmaxEnc[c]));
                g_chunkbound[b * NCHUNK + c] = bound;
            }
        }
    }
}

// ---- raster: 16x8 tile per block; SPLIT blocks per tile over interleaved chunks ----
__global__ void __launch_bounds__(NTHR) raster() {
    __shared__ float4 sQ0[TF], sQ1[TF], sQ2[TF];
    __shared__ int scount;
    __shared__ unsigned sminEnc[2];

    const int b = blockIdx.z / SPLIT;
    const int sp = blockIdx.z % SPLIT;
    const int tid = threadIdx.x;
    const int tx = tid & 15;
    const int ty = tid >> 4;

    const int pxi = blockIdx.x * 16 + tx;
    const int pyi = blockIdx.y * 8 + ty;
    const int pix = pyi * IW + pxi;

    const float px = ((float)pxi + 0.5f) / 256.0f * 2.0f - 1.0f;
    const float py = ((float)pyi + 0.5f) / 256.0f * 2.0f - 1.0f;

    const float eps = 1e-4f;
    const float blk_xmin = (blockIdx.x * 16 + 0.5f)  / 256.0f * 2.0f - 1.0f - eps;
    const float blk_xmax = (blockIdx.x * 16 + 15.5f) / 256.0f * 2.0f - 1.0f + eps;
    const float blk_ymin = (blockIdx.y * 8 + 0.5f)   / 256.0f * 2.0f - 1.0f - eps;
    const float blk_ymax = (blockIdx.y * 8 + 7.5f)   / 256.0f * 2.0f - 1.0f + eps;

    float bz = -1.0f;
    int bf = -1;
    float warpmin = -1.0f;
    float blockmin_prev = -1.0f;
    int it = 0;

    for (int c = sp; c < NCHUNK; c += SPLIT, it++) {
        const int base = c * TF;
        if (tid == 0) scount = 0;
        if (tid == 32) sminEnc[it & 1] = 0xFFFFFFFFu;
        __syncthreads();

        const float cbound = g_chunkbound[b * NCHUNK + c];
        if (it > 0) {
            blockmin_prev = decf(sminEnc[(it - 1) & 1]);
            if (cbound < blockmin_prev) break;
        }

#pragma unroll
        for (int k = 0; k < TF / NTHR; k++) {
            int r = b * NF + base + tid + k * NTHR;
            float4 qb = g_qb[r];
            if (qb.y >= blk_xmin && qb.x <= blk_xmax && qb.w >= blk_ymin && qb.z <= blk_ymax) {
                float4 q1 = g_q1[r];
                if (q1.w < blockmin_prev) continue;
                float4 q0 = g_q0[r];
                const float inv = q1.z;
                float a0 = q0.x * inv, b0 = q0.y * inv;
                float a1 = q0.z * inv, b1 = q0.w * inv;
                float c0 = -(a0 * q1.x + b0 * q1.y);
                float c1 = -(a1 * q1.x + b1 * q1.y);
                float maxw0 = fmaxf(a0 * blk_xmin, a0 * blk_xmax)
                            + fmaxf(b0 * blk_ymin, b0 * blk_ymax) + c0;
                float maxw1 = fmaxf(a1 * blk_xmin, a1 * blk_xmax)
                            + fmaxf(b1 * blk_ymin, b1 * blk_ymax) + c1;
                float a2 = -(a0 + a1), b2 = -(b0 + b1), c2 = 1.0f - c0 - c1;
                float maxw2 = fmaxf(a2 * blk_xmin, a2 * blk_xmax)
                            + fmaxf(b2 * blk_ymin, b2 * blk_ymax) + c2;
                const float m = -1e-5f;
                if (maxw0 < m || maxw1 < m || maxw2 < m) continue;
                int slot = atomicAdd(&scount, 1);
                sQ0[slot] = q0;
                sQ1[slot] = q1;
                sQ2[slot] = g_q2[r];
            }
        }
        __syncthreads();

        const int cnt = scount;
        if (cbound >= warpmin) {
            for (int j = 0; j < cnt; j++) {
                float4 q1 = sQ1[j];
                if (q1.w < bz) continue;
                float4 q0 = sQ0[j];
                float4 q2 = sQ2[j];
                const float inv = q1.z;
                const float dx = px - q1.x;
                const float dy = py - q1.y;
                float w0 = (q0.x * dx + q0.y * dy) * inv;
                float w1 = (q0.z * dx + q0.w * dy) * inv;
                float w2 = 1.0f - w0 - w1;
                if (w0 >= 0.0f && w1 >= 0.0f && w2 >= 0.0f) {
                    float z = w0 * q2.x + w1 * q2.y + w2 * q2.z;
                    int f2 = __float_as_int(q2.w);
                    if (z > bz || (z == bz && bf >= 0 && f2 < bf)) {
                        bz = z; bf = f2;
                    }
                }
            }
        }

        float v = bz;
#pragma unroll
        for (int s = 16; s > 0; s >>= 1)
            v = fminf(v, __shfl_xor_sync(0xffffffffu, v, s));
        warpmin = v;
        if ((tid & 31) == 0) atomicMin(&sminEnc[it & 1], encf(v));
    }

    // merge: lexicographic (z, -fid) max — exact scan/argmax semantics
    if (bf >= 0) {
        unsigned long long v = ((unsigned long long)encf(bz) << 32)
                             | (unsigned long long)(~(unsigned)bf);
        atomicMax(&g_zfid[(size_t)b * PP + pix], v);
    }
}

// ---- shade: 1 px/thread; 2-level chain via per-face attr table ----
#define SHADE_THR 256
__global__ void __launch_bounds__(SHADE_THR) shade(float* __restrict__ out) {
    int idx = blockIdx.x * SHADE_THR + threadIdx.x;
    if (idx >= NB * PP) return;
    const int b = idx / PP;
    const int pix = idx % PP;
    const int pxi = pix & 255;
    const int pyi = pix >> 8;
    const float px = ((float)pxi + 0.5f) / 256.0f * 2.0f - 1.0f;
    const float py = ((float)pyi + 0.5f) / 256.0f * 2.0f - 1.0f;

    unsigned long long v = g_zfid[idx];
    float fz = decf((unsigned)(v >> 32));
    int ff = (int)(~(unsigned)(v & 0xFFFFFFFFu));

    const float alpha = (ff >= 0) ? 1.0f : 0.0f;
    const int sf = (ff >= 0) ? ff : 0;
    const float4* fa = &g_fattr[6 * (b * NF + sf)];
    float4 a0  = fa[0];
    float4 a0b = fa[1];
    float4 a1  = fa[2];
    float4 a1b = fa[3];
    float4 a2  = fa[4];
    float4 a2b = fa[5];

    float bw0 = 0.0f, bw1 = 0.0f, bw2 = 0.0f;
    if (ff >= 0) {
        float x0 = a0b.z, y0 = a0b.w;
        float x1 = a1b.z, y1 = a1b.w;
        float x2 = a2b.z, y2 = a2b.w;
        float denom = (y1 - y2) * (x0 - x2) + (x2 - x1) * (y0 - y2);
        float inv = (fabsf(denom) > 1e-8f) ? (1.0f / denom) : 0.0f;
        float dx = px - x2;
        float dy = py - y2;
        bw0 = ((y1 - y2) * dx + (x2 - x1) * dy) * inv;
        bw1 = ((y2 - y0) * dx + (x0 - x2) * dy) * inv;
        bw2 = 1.0f - bw0 - bw1;
    }

    float ch[6];
    ch[0] = a0.x * bw0 + a1.x * bw1 + a2.x * bw2;
    ch[1] = a0.y * bw0 + a1.y * bw1 + a2.y * bw2;
    ch[2] = a0.z * bw0 + a1.z * bw1 + a2.z * bw2;
    ch[3] = a0.w * bw0 + a1.w * bw1 + a2.w * bw2;
    ch[4] = a0b.x * bw0 + a1b.x * bw1 + a2b.x * bw2;
    ch[5] = a0b.y * bw0 + a1b.y * bw1 + a2b.y * bw2;

    float* rend = out;
    float* al   = out + (size_t)NB * 6 * PP;
    float* fo   = al  + (size_t)NB * PP;
    float* zo   = fo  + (size_t)NB * PP;

#pragma unroll
    for (int c = 0; c < 6; c++)
        rend[((size_t)b * 6 + c) * PP + pix] = ch[c] * alpha;
    al[(size_t)b * PP + pix] = alpha;
    fo[(size_t)b * PP + pix] = (float)ff;
    zo[(size_t)b * PP + pix] = fz;
}

extern "C" void kernel_launch(void* const* d_in, const int* in_sizes, int n_in,
                              void* d_out, int out_size) {
    const float* vertices = (const float*)d_in[0];
    const float* tverts   = (const float*)d_in[1];
    const float* tex      = (const float*)d_in[2];
    const float* uv       = (const float*)d_in[3];
    const int*   faces    = (const int*)d_in[4];
    float* out = (float*)d_out;

    preA<<<FACE_BLKS + FATTR_BLKS + ZINIT_BLKS, PREA_THR>>>(tverts, faces, tex, uv, vertices);
    preB<<<NB, SORT_THR>>>();
    dim3 grid(IW / 16, IH / 8, NB * SPLIT);
    raster<<<grid, NTHR>>>();
    shade<<<(NB * PP + SHADE_THR - 1) / SHADE_THR, SHADE_THR>>>(out);
}

// round 14
// speedup vs baseline: 1.5672x; 1.5672x over previous
#include <cuda_runtime.h>
#include <math.h>

// Problem constants
#define NB 2
#define NV 5023
#define NF 2048
#define IH 256
#define IW 256
#define PP (IH * IW)
#define TF 256               // faces per smem chunk
#define NCHUNK (NF / TF)     // 8
#define SPLIT 2              // face-partition blocks per tile
#define NTHR 128
#define SORT_THR 1024
#define FPB (NF / SORT_THR)  // 2

#define PREA_THR 256
#define FACE_BLKS ((NB * NF + PREA_THR - 1) / PREA_THR)                   // 16

// preB heterogeneous layout (1024 threads/block)
#define FATTR_BLKS ((NB * NF * 3 + SORT_THR - 1) / SORT_THR)              // 12
#define ZINIT_PER 8
#define ZINIT_BLKS ((NB * PP + SORT_THR * ZINIT_PER - 1) / (SORT_THR * ZINIT_PER)) // 16

// Unsorted face records (written by preA)
__device__ float4 g_u0[NB * NF];
__device__ float4 g_u1[NB * NF];
__device__ float4 g_u2[NB * NF];
__device__ float4 g_ub[NB * NF];
// Sorted face records (written by preB)
__device__ float4 g_q0[NB * NF];  // A0,B0,A1,B1
__device__ float4 g_q1[NB * NF];  // x2,y2,inv,zmax
__device__ float4 g_q2[NB * NF];  // z0,z1,z2,face_id(bits)
__device__ float4 g_qb[NB * NF];  // xmin,xmax,ymin,ymax
__device__ float g_chunkbound[NB * NCHUNK];   // per-parity suffix max
// Per-face shading attrs: 6 x float4 per (b,f)
__device__ float4 g_fattr[6 * NB * NF];
__device__ unsigned long long g_zfid[NB * PP]; // (enc(z)<<32)|~fid

__device__ __forceinline__ unsigned encf(float x) {
    unsigned u = __float_as_uint(x);
    return (u & 0x80000000u) ? ~u : (u | 0x80000000u);
}
__device__ __forceinline__ float decf(unsigned e) {
    unsigned u = (e & 0x80000000u) ? (e & 0x7FFFFFFFu) : ~e;
    return __uint_as_float(u);
}
__device__ __forceinline__ int zbucket(float zmx) {
    int bi = (int)((1.0f - zmx) * 127.5f);
    return min(max(bi, 0), 255);
}

// bilinear texture sample for one vertex (reference expression tree)
__device__ __forceinline__ void sample_vcol(const float* __restrict__ tex,
                                            const float* __restrict__ uv,
                                            int b, int v, float col[3]) {
    float u = uv[v * 2 + 0] * 255.0f;
    float vv = uv[v * 2 + 1] * 255.0f;
    float u0f = floorf(u);
    float v0f = floorf(vv);
    u0f = fminf(fmaxf(u0f, 0.0f), 254.0f);
    v0f = fminf(fmaxf(v0f, 0.0f), 254.0f);
    int u0 = (int)u0f;
    int v0 = (int)v0f;
    float fu = u - u0f;
    float fv = vv - v0f;
    const float* t = tex + (size_t)b * 256 * 256 * 3;
    const float* r0 = t + ((size_t)v0 * 256 + u0) * 3;
    const float* r1 = t + ((size_t)(v0 + 1) * 256 + u0) * 3;
#pragma unroll
    for (int c = 0; c < 3; c++) {
        float c00 = r0[c];
        float c01 = r0[3 + c];
        float c10 = r1[c];
        float c11 = r1[3 + c];
        float top = c00 * (1.0f - fu) + c01 * fu;
        float bot = c10 * (1.0f - fu) + c11 * fu;
        col[c] = top * (1.0f - fv) + bot * fv;
    }
}

// ---- preA: face records ONLY (lean; everything else moved to preB) ----
__global__ void __launch_bounds__(PREA_THR) preA(const float* __restrict__ tv,
                                                 const int* __restrict__ faces) {
    int idx = blockIdx.x * PREA_THR + threadIdx.x;
    if (idx >= NB * NF) return;
    int b = idx / NF, f = idx % NF;
    int i0 = faces[f * 3 + 0];
    int i1 = faces[f * 3 + 1];
    int i2 = faces[f * 3 + 2];
    const float* p0 = tv + ((size_t)b * NV + i0) * 3;
    const float* p1 = tv + ((size_t)b * NV + i1) * 3;
    const float* p2 = tv + ((size_t)b * NV + i2) * 3;
    float x0 = p0[0], y0 = p0[1], z0 = p0[2];
    float x1 = p1[0], y1 = p1[1], z1 = p1[2];
    float x2 = p2[0], y2 = p2[1], z2 = p2[2];

    float denom = (y1 - y2) * (x0 - x2) + (x2 - x1) * (y0 - y2);
    bool valid = fabsf(denom) > 1e-8f;
    float inv = valid ? (1.0f / denom) : 0.0f;

    float xmn = fminf(x0, fminf(x1, x2));
    float xmx = fmaxf(x0, fmaxf(x1, x2));
    float ymn = fminf(y0, fminf(y1, y2));
    float ymx = fmaxf(y0, fmaxf(y1, y2));
    float zmx = fmaxf(z0, fmaxf(z1, z2));
    if (!valid) { xmn = 2e30f; xmx = -2e30f; ymn = 2e30f; ymx = -2e30f; zmx = -3e30f; }

    g_u0[idx] = make_float4(y1 - y2, x2 - x1, y2 - y0, x0 - x2);
    g_u1[idx] = make_float4(x2, y2, inv, zmx);
    g_u2[idx] = make_float4(z0, z1, z2, __int_as_float(f));
    g_ub[idx] = make_float4(xmn, xmx, ymn, ymx);
}

// ---- preB: sort (blocks [0,NB)) ∥ fattr build ∥ zfid init ----
__global__ void __launch_bounds__(SORT_THR) preB(const float* __restrict__ tv,
                                                 const int* __restrict__ faces,
                                                 const float* __restrict__ tex,
                                                 const float* __restrict__ uv,
                                                 const float* __restrict__ verts) {
    const int tid = threadIdx.x;

    if (blockIdx.x >= NB + FATTR_BLKS) {
        // ---- zfid init (independent of preA) ----
        const unsigned long long initv = ((unsigned long long)encf(-1.0f) << 32) | 0ull;
        int base = (blockIdx.x - NB - FATTR_BLKS) * SORT_THR * ZINIT_PER + tid;
#pragma unroll
        for (int k = 0; k < ZINIT_PER; k++) {
            int i = base + k * SORT_THR;
            if (i < NB * PP) g_zfid[i] = initv;
        }
        return;
    }

    if (blockIdx.x >= NB) {
        // ---- fattr build: one thread per (b, f, k) — independent of preA ----
        int idx = (blockIdx.x - NB) * SORT_THR + tid;
        if (idx >= NB * NF * 3) return;
        int b = idx / (NF * 3);
        int rem = idx % (NF * 3);
        int f = rem / 3;
        int k = rem % 3;
        int vid = faces[f * 3 + k];
        float col[3];
        sample_vcol(tex, uv, b, vid, col);
        const float* vp = verts + ((size_t)(b * NV + vid)) * 3;
        const float* tp = tv + ((size_t)(b * NV + vid)) * 3;
        int go = 6 * (b * NF + f) + 2 * k;
        g_fattr[go + 0] = make_float4(col[0], col[1], col[2], vp[0]);
        g_fattr[go + 1] = make_float4(vp[1], vp[2], tp[0], tp[1]);
        return;
    }

    // ---- counting sort (one block per batch) ----
    __shared__ int hist[256];
    __shared__ int offs[256];
    __shared__ int warpTot[8];
    __shared__ unsigned chunkmaxEnc[NCHUNK];
    const int b = blockIdx.x;

    if (tid < 256) hist[tid] = 0;
    if (tid < NCHUNK) chunkmaxEnc[tid] = 0u;

    float4 rq0[FPB], rq1[FPB], rq2[FPB], rqb[FPB];
    int rbkt[FPB];
#pragma unroll
    for (int k = 0; k < FPB; k++) {
        int gi = b * NF + tid + k * SORT_THR;
        rq0[k] = g_u0[gi];
        rq1[k] = g_u1[gi];
        rq2[k] = g_u2[gi];
        rqb[k] = g_ub[gi];
        rbkt[k] = zbucket(rq1[k].w);
    }
    __syncthreads();

#pragma unroll
    for (int k = 0; k < FPB; k++) atomicAdd(&hist[rbkt[k]], 1);
    __syncthreads();

    // hierarchical exclusive scan over 256 buckets (3 syncs)
    int myVal = 0, wIncl = 0;
    if (tid < 256) {
        myVal = hist[tid];
        wIncl = myVal;
#pragma unroll
        for (int s = 1; s < 32; s <<= 1) {
            int n = __shfl_up_sync(0xffffffffu, wIncl, s);
            if ((tid & 31) >= s) wIncl += n;
        }
        if ((tid & 31) == 31) warpTot[tid >> 5] = wIncl;
    }
    __syncthreads();
    if (tid < 8) {
        int t = warpTot[tid];
        int incl = t;
#pragma unroll
        for (int s = 1; s < 8; s <<= 1) {
            int n = __shfl_up_sync(0xffu, incl, s);
            if (tid >= s) incl += n;
        }
        warpTot[tid] = incl - t;
    }
    __syncthreads();
    if (tid < 256) offs[tid] = warpTot[tid >> 5] + wIncl - myVal;
    __syncthreads();

#pragma unroll
    for (int k = 0; k < FPB; k++) {
        int pos = atomicAdd(&offs[rbkt[k]], 1);
        int go = b * NF + pos;
        g_q0[go] = rq0[k];
        g_q1[go] = rq1[k];
        g_q2[go] = rq2[k];
        g_qb[go] = rqb[k];
        atomicMax(&chunkmaxEnc[pos / TF], encf(rq1[k].w));
    }
    __syncthreads();

    if (tid == 0) {
#pragma unroll
        for (int s = 0; s < SPLIT; s++) {
            float bound = -3e30f;
            for (int c = NCHUNK - SPLIT + s; c >= 0; c -= SPLIT) {
                bound = fmaxf(bound, decf(chunkmaxEnc[c]));
                g_chunkbound[b * NCHUNK + c] = bound;
            }
        }
    }
}

// ---- raster: 16x8 tile per block; SPLIT blocks per tile over interleaved chunks ----
__global__ void __launch_bounds__(NTHR) raster() {
    __shared__ float4 sQ0[TF], sQ1[TF], sQ2[TF];
    __shared__ int scount;
    __shared__ unsigned sminEnc[2];

    const int b = blockIdx.z / SPLIT;
    const int sp = blockIdx.z % SPLIT;
    const int tid = threadIdx.x;
    const int tx = tid & 15;
    const int ty = tid >> 4;

    const int pxi = blockIdx.x * 16 + tx;
    const int pyi = blockIdx.y * 8 + ty;
    const int pix = pyi * IW + pxi;

    const float px = ((float)pxi + 0.5f) / 256.0f * 2.0f - 1.0f;
    const float py = ((float)pyi + 0.5f) / 256.0f * 2.0f - 1.0f;

    const float eps = 1e-4f;
    const float blk_xmin = (blockIdx.x * 16 + 0.5f)  / 256.0f * 2.0f - 1.0f - eps;
    const float blk_xmax = (blockIdx.x * 16 + 15.5f) / 256.0f * 2.0f - 1.0f + eps;
    const float blk_ymin = (blockIdx.y * 8 + 0.5f)   / 256.0f * 2.0f - 1.0f - eps;
    const float blk_ymax = (blockIdx.y * 8 + 7.5f)   / 256.0f * 2.0f - 1.0f + eps;

    float bz = -1.0f;
    int bf = -1;
    float warpmin = -1.0f;
    float blockmin_prev = -1.0f;
    int it = 0;

    for (int c = sp; c < NCHUNK; c += SPLIT, it++) {
        const int base = c * TF;
        if (tid == 0) scount = 0;
        if (tid == 32) sminEnc[it & 1] = 0xFFFFFFFFu;
        __syncthreads();

        const float cbound = g_chunkbound[b * NCHUNK + c];
        if (it > 0) {
            blockmin_prev = decf(sminEnc[(it - 1) & 1]);
            if (cbound < blockmin_prev) break;
        }

#pragma unroll
        for (int k = 0; k < TF / NTHR; k++) {
            int r = b * NF + base + tid + k * NTHR;
            float4 qb = g_qb[r];
            if (qb.y >= blk_xmin && qb.x <= blk_xmax && qb.w >= blk_ymin && qb.z <= blk_ymax) {
                float4 q1 = g_q1[r];
                if (q1.w < blockmin_prev) continue;
                float4 q0 = g_q0[r];
                const float inv = q1.z;
                float a0 = q0.x * inv, b0 = q0.y * inv;
                float a1 = q0.z * inv, b1 = q0.w * inv;
                float c0 = -(a0 * q1.x + b0 * q1.y);
                float c1 = -(a1 * q1.x + b1 * q1.y);
                float maxw0 = fmaxf(a0 * blk_xmin, a0 * blk_xmax)
                            + fmaxf(b0 * blk_ymin, b0 * blk_ymax) + c0;
                float maxw1 = fmaxf(a1 * blk_xmin, a1 * blk_xmax)
                            + fmaxf(b1 * blk_ymin, b1 * blk_ymax) + c1;
                float a2 = -(a0 + a1), b2 = -(b0 + b1), c2 = 1.0f - c0 - c1;
                float maxw2 = fmaxf(a2 * blk_xmin, a2 * blk_xmax)
                            + fmaxf(b2 * blk_ymin, b2 * blk_ymax) + c2;
                const float m = -1e-5f;
                if (maxw0 < m || maxw1 < m || maxw2 < m) continue;
                int slot = atomicAdd(&scount, 1);
                sQ0[slot] = q0;
                sQ1[slot] = q1;
                sQ2[slot] = g_q2[r];
            }
        }
        __syncthreads();

        const int cnt = scount;
        if (cbound >= warpmin) {
            for (int j = 0; j < cnt; j++) {
                float4 q1 = sQ1[j];
                if (q1.w < bz) continue;
                float4 q0 = sQ0[j];
                float4 q2 = sQ2[j];
                const float inv = q1.z;
                const float dx = px - q1.x;
                const float dy = py - q1.y;
                float w0 = (q0.x * dx + q0.y * dy) * inv;
                float w1 = (q0.z * dx + q0.w * dy) * inv;
                float w2 = 1.0f - w0 - w1;
                if (w0 >= 0.0f && w1 >= 0.0f && w2 >= 0.0f) {
                    float z = w0 * q2.x + w1 * q2.y + w2 * q2.z;
                    int f2 = __float_as_int(q2.w);
                    if (z > bz || (z == bz && bf >= 0 && f2 < bf)) {
                        bz = z; bf = f2;
                    }
                }
            }
        }

        float v = bz;
#pragma unroll
        for (int s = 16; s > 0; s >>= 1)
            v = fminf(v, __shfl_xor_sync(0xffffffffu, v, s));
        warpmin = v;
        if ((tid & 31) == 0) atomicMin(&sminEnc[it & 1], encf(v));
    }

    // merge: lexicographic (z, -fid) max — exact scan/argmax semantics
    if (bf >= 0) {
        unsigned long long v = ((unsigned long long)encf(bz) << 32)
                             | (unsigned long long)(~(unsigned)bf);
        atomicMax(&g_zfid[(size_t)b * PP + pix], v);
    }
}

// ---- shade: 1 px/thread; 2-level chain via per-face attr table ----
#define SHADE_THR 256
__global__ void __launch_bounds__(SHADE_THR) shade(float* __restrict__ out) {
    int idx = blockIdx.x * SHADE_THR + threadIdx.x;
    if (idx >= NB * PP) return;
    const int b = idx / PP;
    const int pix = idx % PP;
    const int pxi = pix & 255;
    const int pyi = pix >> 8;
    const float px = ((float)pxi + 0.5f) / 256.0f * 2.0f - 1.0f;
    const float py = ((float)pyi + 0.5f) / 256.0f * 2.0f - 1.0f;

    unsigned long long v = g_zfid[idx];
    float fz = decf((unsigned)(v >> 32));
    int ff = (int)(~(unsigned)(v & 0xFFFFFFFFu));

    const float alpha = (ff >= 0) ? 1.0f : 0.0f;
    const int sf = (ff >= 0) ? ff : 0;
    const float4* fa = &g_fattr[6 * (b * NF + sf)];
    float4 a0  = fa[0];
    float4 a0b = fa[1];
    float4 a1  = fa[2];
    float4 a1b = fa[3];
    float4 a2  = fa[4];
    float4 a2b = fa[5];

    float bw0 = 0.0f, bw1 = 0.0f, bw2 = 0.0f;
    if (ff >= 0) {
        float x0 = a0b.z, y0 = a0b.w;
        float x1 = a1b.z, y1 = a1b.w;
        float x2 = a2b.z, y2 = a2b.w;
        float denom = (y1 - y2) * (x0 - x2) + (x2 - x1) * (y0 - y2);
        float inv = (fabsf(denom) > 1e-8f) ? (1.0f / denom) : 0.0f;
        float dx = px - x2;
        float dy = py - y2;
        bw0 = ((y1 - y2) * dx + (x2 - x1) * dy) * inv;
        bw1 = ((y2 - y0) * dx + (x0 - x2) * dy) * inv;
        bw2 = 1.0f - bw0 - bw1;
    }

    float ch[6];
    ch[0] = a0.x * bw0 + a1.x * bw1 + a2.x * bw2;
    ch[1] = a0.y * bw0 + a1.y * bw1 + a2.y * bw2;
    ch[2] = a0.z * bw0 + a1.z * bw1 + a2.z * bw2;
    ch[3] = a0.w * bw0 + a1.w * bw1 + a2.w * bw2;
    ch[4] = a0b.x * bw0 + a1b.x * bw1 + a2b.x * bw2;
    ch[5] = a0b.y * bw0 + a1b.y * bw1 + a2b.y * bw2;

    float* rend = out;
    float* al   = out + (size_t)NB * 6 * PP;
    float* fo   = al  + (size_t)NB * PP;
    float* zo   = fo  + (size_t)NB * PP;

#pragma unroll
    for (int c = 0; c < 6; c++)
        rend[((size_t)b * 6 + c) * PP + pix] = ch[c] * alpha;
    al[(size_t)b * PP + pix] = alpha;
    fo[(size_t)b * PP + pix] = (float)ff;
    zo[(size_t)b * PP + pix] = fz;
}

extern "C" void kernel_launch(void* const* d_in, const int* in_sizes, int n_in,
                              void* d_out, int out_size) {
    const float* vertices = (const float*)d_in[0];
    const float* tverts   = (const float*)d_in[1];
    const float* tex      = (const float*)d_in[2];
    const float* uv       = (const float*)d_in[3];
    const int*   faces    = (const int*)d_in[4];
    float* out = (float*)d_out;

    preA<<<FACE_BLKS, PREA_THR>>>(tverts, faces);
    preB<<<NB + FATTR_BLKS + ZINIT_BLKS, SORT_THR>>>(tverts, faces, tex, uv, vertices);
    dim3 grid(IW / 16, IH / 8, NB * SPLIT);
    raster<<<grid, NTHR>>>();
    shade<<<(NB * PP + SHADE_THR - 1) / SHADE_THR, SHADE_THR>>>(out);
}